// round 6
// baseline (speedup 1.0000x reference)
#include <cuda_runtime.h>

// Problem constants (fixed by the reference)
#define NN 50000
#define EE 800000
#define DD 64
#define KK 3

// ---------------- scratch (static __device__ arrays; no allocation) ----------
__device__ float g_Ax[NN * DD];        // 12.8 MB
__device__ float g_Dx[NN * DD];        // 12.8 MB
__device__ float g_Bx[KK * NN * DD];   // 38.4 MB
__device__ float g_xnew[NN * DD];      // 12.8 MB
__device__ int   g_head[NN * KK];      // 0.6 MB  per-(node,k) linked-list heads
__device__ int   g_next[EE];           // 3.2 MB  linked-list next pointers
__device__ float g_sum[DD];            // BN: per-feature sum
__device__ float g_sq[DD];             // BN: per-feature sum of squares

// ---------------- kernel 0: reset per-launch state --------------------------
__global__ void k_init() {
    int i = blockIdx.x * blockDim.x + threadIdx.x;
    if (i < NN * KK) g_head[i] = -1;
    if (i < DD) { g_sum[i] = 0.f; g_sq[i] = 0.f; }
}

// ---------------- kernel 1: fused 5x GEMM (Ax, Dx, Bx[0..2]) ----------------
// block: 32 nodes, blockDim (64, 8); each thread computes 4 node outputs for
// one output feature. xs tiles + one W matrix live in shared memory.
__device__ __forceinline__ void gemm_job(
    const float (*xsl)[DD], float (*Wsh)[DD],
    const float* __restrict__ W, const float* __restrict__ b,
    float* __restrict__ out, int nb, int tx, int ty, int tid)
{
    __syncthreads();
    for (int idx = tid; idx < DD * DD; idx += 512)
        Wsh[idx >> 6][idx & 63] = W[idx];
    __syncthreads();

    float acc[4] = {0.f, 0.f, 0.f, 0.f};
    #pragma unroll 16
    for (int d = 0; d < DD; d++) {
        float w = Wsh[d][tx];            // conflict-free: tx consecutive
        acc[0] += xsl[ty     ][d] * w;   // broadcast reads
        acc[1] += xsl[ty +  8][d] * w;
        acc[2] += xsl[ty + 16][d] * w;
        acc[3] += xsl[ty + 24][d] * w;
    }
    float bv = b[tx];
    #pragma unroll
    for (int m = 0; m < 4; m++) {
        int n = nb + ty + 8 * m;
        if (n < NN) out[n * DD + tx] = acc[m] + bv;
    }
}

__global__ __launch_bounds__(512) void k_gemm(
    const float* __restrict__ xs,
    const float* __restrict__ Wa, const float* __restrict__ ba,
    const float* __restrict__ Wd, const float* __restrict__ bd,
    const float* __restrict__ Wb, const float* __restrict__ bb)
{
    __shared__ float xsh[3][32][DD];   // 24 KB: xs[0..2] tiles for 32 nodes
    __shared__ float Wsh[DD][DD];      // 16 KB: current weight matrix

    int tx = threadIdx.x;              // 0..63: output feature
    int ty = threadIdx.y;              // 0..7
    int tid = ty * 64 + tx;
    int nb = blockIdx.x * 32;

    for (int idx = tid; idx < 3 * 32 * DD; idx += 512) {
        int s   = idx / (32 * DD);
        int rem = idx % (32 * DD);
        int n = rem >> 6, d = rem & 63;
        int gn = nb + n;
        xsh[s][n][d] = (gn < NN) ? xs[s * NN * DD + gn * DD + d] : 0.f;
    }

    // Ax = xs[2]@Wa ; Dx = xs[2]@Wd ; Bx0 = xs[2]@Wb0 ; Bx1 = xs[1]@Wb1 ; Bx2 = xs[0]@Wb2
    gemm_job(xsh[2], Wsh, Wa,              ba,          g_Ax,              nb, tx, ty, tid);
    gemm_job(xsh[2], Wsh, Wd,              bd,          g_Dx,              nb, tx, ty, tid);
    gemm_job(xsh[2], Wsh, Wb,              bb,          g_Bx,              nb, tx, ty, tid);
    gemm_job(xsh[1], Wsh, Wb +     DD*DD,  bb +     DD, g_Bx +     NN*DD,  nb, tx, ty, tid);
    gemm_job(xsh[0], Wsh, Wb + 2 * DD*DD,  bb + 2 * DD, g_Bx + 2 * NN*DD,  nb, tx, ty, tid);
}

// ---------------- kernel 2: build per-(dst,k) edge linked lists --------------
__global__ void k_link(const int* __restrict__ ei, const int* __restrict__ ea) {
    int e = blockIdx.x * blockDim.x + threadIdx.x;
    if (e >= EE) return;
    int dst = ei[EE + e];              // edge_index[1] = destination i
    int k   = ea[e] - 1;               // hop index 0..2
    int seg = dst * KK + k;
    g_next[e] = atomicExch(&g_head[seg], e);
}

// ---------------- kernel 3: segmented gated aggregation ----------------------
// One block per node: blockDim (64, 3). Thread (tx, k) walks the (node, k)
// edge chain, accumulating num/den in registers. No float atomics anywhere.
__global__ __launch_bounds__(192) void k_agg(const int* __restrict__ ei) {
    int n  = blockIdx.x;
    int tx = threadIdx.x;              // feature dim
    int k  = threadIdx.y;              // hop 0..2

    float dx = g_Dx[n * DD + tx];
    const float* __restrict__ Bk = g_Bx + k * NN * DD;

    int e = g_head[n * KK + k];
    float num = 0.f, den = 0.f;
    while (e >= 0) {
        int en = g_next[e];            // issue chain load first (latency)
        int j  = __ldg(&ei[e]);        // edge_index[0] = source j
        float b = __ldg(&Bk[j * DD + tx]);
        float z = dx + b;
        float s = 1.f / (1.f + __expf(-z));
        num += s * b;
        den += s;
        e = en;
    }
    float eta = num / (den + 1e-6f);   // empty segment -> 0, matches reference

    __shared__ float sh[KK][DD];
    sh[k][tx] = eta;
    __syncthreads();
    if (k == 0) {
        float xn = g_Ax[n * DD + tx]
                 + (1.f / 3.f) * (sh[0][tx] + sh[1][tx] + sh[2][tx]);
        g_xnew[n * DD + tx] = xn;
    }
}

// ---------------- kernel 4: BN statistics (two-level reduction) --------------
__global__ __launch_bounds__(256) void k_stats() {
    int d = threadIdx.x & 63;
    int r = threadIdx.x >> 6;          // 0..3 node-row groups
    float s = 0.f, s2 = 0.f;
    for (int n = blockIdx.x * 4 + r; n < NN; n += gridDim.x * 4) {
        float x = g_xnew[n * DD + d];  // coalesced 256B per 64-thread group
        s += x; s2 += x * x;
    }
    __shared__ float sh1[256], sh2[256];
    sh1[threadIdx.x] = s; sh2[threadIdx.x] = s2;
    __syncthreads();
    if (threadIdx.x < 64) {
        float a = sh1[threadIdx.x] + sh1[threadIdx.x + 64]
                + sh1[threadIdx.x + 128] + sh1[threadIdx.x + 192];
        float b = sh2[threadIdx.x] + sh2[threadIdx.x + 64]
                + sh2[threadIdx.x + 128] + sh2[threadIdx.x + 192];
        atomicAdd(&g_sum[d], a);
        atomicAdd(&g_sq[d], b);
    }
}

// ---------------- kernel 5: BatchNorm + ReLU epilogue ------------------------
__global__ void k_final(const float* __restrict__ gamma,
                        const float* __restrict__ beta,
                        float* __restrict__ out) {
    int i = blockIdx.x * blockDim.x + threadIdx.x;
    if (i >= NN * DD) return;
    int d = i & 63;
    float mean = g_sum[d] * (1.f / NN);
    float var  = g_sq[d] * (1.f / NN) - mean * mean;   // biased var (jnp.var)
    float x = g_xnew[i];
    float y = gamma[d] * (x - mean) * rsqrtf(var + 1e-5f) + beta[d];
    out[i] = fmaxf(y, 0.f);
}

// ---------------- launcher ---------------------------------------------------
extern "C" void kernel_launch(void* const* d_in, const int* in_sizes, int n_in,
                              void* d_out, int out_size) {
    const float* xs    = (const float*)d_in[0];   // [3, N, D]
    const int*   ei    = (const int*)  d_in[1];   // [2, E]
    const int*   ea    = (const int*)  d_in[2];   // [E]
    const float* Wa    = (const float*)d_in[3];
    const float* ba    = (const float*)d_in[4];
    const float* Wd    = (const float*)d_in[5];
    const float* bd    = (const float*)d_in[6];
    const float* Wb    = (const float*)d_in[7];   // [K, D, D]
    const float* bb    = (const float*)d_in[8];   // [K, D]
    const float* gamma = (const float*)d_in[9];
    const float* beta  = (const float*)d_in[10];
    float* out = (float*)d_out;

    k_init <<<(NN * KK + 255) / 256, 256>>>();
    k_gemm <<<(NN + 31) / 32, dim3(64, 8)>>>(xs, Wa, ba, Wd, bd, Wb, bb);
    k_link <<<(EE + 255) / 256, 256>>>(ei, ea);
    k_agg  <<<NN, dim3(64, 3)>>>(ei);
    k_stats<<<232, 256>>>();
    k_final<<<(NN * DD + 255) / 256, 256>>>(gamma, beta, out);
}

// round 7
// speedup vs baseline: 1.2893x; 1.2893x over previous
#include <cuda_runtime.h>

// Problem constants (fixed by the reference)
#define NN 50000
#define EE 800000
#define DD 64
#define KK 3
#define NSEG (NN * KK)          // 150000
#define SCAN_BS 1024
#define NBLK_SCAN ((NSEG + SCAN_BS - 1) / SCAN_BS)   // 147
#define NSEG_PAD (NBLK_SCAN * SCAN_BS)               // 150528

typedef unsigned long long ull;

// ---------------- scratch (static __device__ arrays; no allocation) ----------
__device__ float g_Ax[NN * DD];
__device__ float g_Dx[NN * DD];
__device__ float g_Bx[KK * NN * DD];
__device__ float g_xnew[NN * DD];
__device__ int   g_cnt[NSEG_PAD];     // per-(node,k) edge counts
__device__ int   g_scan[NSEG_PAD];    // block-local inclusive scan
__device__ int   g_btot[NBLK_SCAN];   // per-block totals
__device__ int   g_boff[NBLK_SCAN];   // exclusive block offsets
__device__ int   g_start[NSEG];       // CSR segment starts
__device__ int   g_cursor[NSEG];      // scatter cursors
__device__ int   g_srcs[EE];          // CSR-sorted source node ids
__device__ float g_sum[DD];
__device__ float g_sq[DD];

// ---------------- kernel 0: reset per-launch state ---------------------------
__global__ void k_init() {
    int i = blockIdx.x * blockDim.x + threadIdx.x;
    if (i < NSEG_PAD) g_cnt[i] = 0;
    if (i < DD) { g_sum[i] = 0.f; g_sq[i] = 0.f; }
}

// ---------------- f32x2 packed-FMA helpers -----------------------------------
__device__ __forceinline__ void ffma2(ull& d, ull a, ull b) {
    asm("fma.rn.f32x2 %0, %1, %2, %0;" : "+l"(d) : "l"(a), "l"(b));
}
__device__ __forceinline__ ull pack_dup(float x) {
    ull r;
    asm("mov.b64 %0, {%1, %1};" : "=l"(r) : "f"(x));
    return r;
}
__device__ __forceinline__ void unpack2(float& lo, float& hi, ull v) {
    asm("mov.b64 {%0, %1}, %2;" : "=f"(lo), "=f"(hi) : "l"(v));
}

// ---------------- kernel 1: fused 5x GEMM (Ax, Dx, Bx[0..2]) -----------------
// Block = 128 threads, node tile = 64. Thread: 4 nodes x 4 feature-pairs,
// accumulators as packed f32x2 (FFMA2 halves FMA-pipe instructions).
__device__ __noinline__ void gemm_job(
    float (*__restrict__ xsh)[65], float (*__restrict__ Wsh)[DD],
    const float* __restrict__ xg,   // global x base, or nullptr to reuse tile
    const float* __restrict__ W, const float* __restrict__ b,
    float* __restrict__ out, int nb)
{
    int tx = threadIdx.x;
    int pg = tx & 7;                 // pair group: features 8*pg .. 8*pg+7
    int ng = tx >> 3;                // node group: nodes ng*4 .. ng*4+3

    __syncthreads();                 // protect previous job's Wsh/xsh use
    if (xg) {
        for (int idx = tx; idx < 64 * DD; idx += 128) {
            int n = idx >> 6, d = idx & 63;
            int gn = nb + n;
            xsh[n][d] = (gn < NN) ? xg[gn * DD + d] : 0.f;
        }
    }
    for (int idx = tx; idx < DD * DD; idx += 128)
        Wsh[idx >> 6][idx & 63] = W[idx];
    __syncthreads();

    ull acc[4][4];
    #pragma unroll
    for (int m = 0; m < 4; m++)
        #pragma unroll
        for (int pp = 0; pp < 4; pp++) acc[m][pp] = 0ull;

    #pragma unroll 16
    for (int d = 0; d < DD; d++) {
        ull w[4];
        #pragma unroll
        for (int pp = 0; pp < 4; pp++)
            w[pp] = *(const ull*)&Wsh[d][8 * pg + 2 * pp];
        #pragma unroll
        for (int m = 0; m < 4; m++) {
            ull x2 = pack_dup(xsh[ng * 4 + m][d]);
            #pragma unroll
            for (int pp = 0; pp < 4; pp++) ffma2(acc[m][pp], x2, w[pp]);
        }
    }

    #pragma unroll
    for (int m = 0; m < 4; m++) {
        int n = nb + ng * 4 + m;
        if (n >= NN) continue;
        #pragma unroll
        for (int pp = 0; pp < 4; pp++) {
            int f = 8 * pg + 2 * pp;
            float lo, hi;
            unpack2(lo, hi, acc[m][pp]);
            float2 v = make_float2(lo + b[f], hi + b[f + 1]);
            *(float2*)&out[n * DD + f] = v;
        }
    }
}

__global__ __launch_bounds__(128) void k_gemm(
    const float* __restrict__ xs,
    const float* __restrict__ Wa, const float* __restrict__ ba,
    const float* __restrict__ Wd, const float* __restrict__ bd,
    const float* __restrict__ Wb, const float* __restrict__ bb)
{
    __shared__ float xsh[64][65];    // padded: node-strided reads conflict-free
    __shared__ float Wsh[DD][DD];
    int nb = blockIdx.x * 64;

    const float* x2g = xs + 2 * NN * DD;
    const float* x1g = xs + 1 * NN * DD;
    const float* x0g = xs;

    // Ax, Dx, Bx0 share xs[2]; Bx1 <- xs[1]; Bx2 <- xs[0]
    gemm_job(xsh, Wsh, x2g, Wa,             ba,          g_Ax,             nb);
    gemm_job(xsh, Wsh, 0,   Wd,             bd,          g_Dx,             nb);
    gemm_job(xsh, Wsh, 0,   Wb,             bb,          g_Bx,             nb);
    gemm_job(xsh, Wsh, x1g, Wb +     DD*DD, bb +     DD, g_Bx +     NN*DD, nb);
    gemm_job(xsh, Wsh, x0g, Wb + 2 * DD*DD, bb + 2 * DD, g_Bx + 2 * NN*DD, nb);
}

// ---------------- CSR build: histogram -> scan -> scatter --------------------
__global__ void k_hist(const int* __restrict__ ei, const int* __restrict__ ea) {
    int e = blockIdx.x * blockDim.x + threadIdx.x;
    if (e >= EE) return;
    int seg = ei[EE + e] * KK + (ea[e] - 1);
    atomicAdd(&g_cnt[seg], 1);
}

__global__ __launch_bounds__(SCAN_BS) void k_scanb() {
    __shared__ int sh[SCAN_BS];
    int t = threadIdx.x;
    int i = blockIdx.x * SCAN_BS + t;
    int v = g_cnt[i];                // padded region is zero
    sh[t] = v;
    __syncthreads();
    for (int o = 1; o < SCAN_BS; o <<= 1) {
        int a = (t >= o) ? sh[t - o] : 0;
        __syncthreads();
        sh[t] += a;
        __syncthreads();
    }
    g_scan[i] = sh[t];               // inclusive within block
    if (t == SCAN_BS - 1) g_btot[blockIdx.x] = sh[t];
}

__global__ __launch_bounds__(256) void k_scant() {
    __shared__ int sh[256];
    int t = threadIdx.x;
    int v = (t < NBLK_SCAN) ? g_btot[t] : 0;
    sh[t] = v;
    __syncthreads();
    for (int o = 1; o < 256; o <<= 1) {
        int a = (t >= o) ? sh[t - o] : 0;
        __syncthreads();
        sh[t] += a;
        __syncthreads();
    }
    if (t < NBLK_SCAN) g_boff[t] = sh[t] - v;   // exclusive
}

__global__ void k_scana() {
    int i = blockIdx.x * blockDim.x + threadIdx.x;
    if (i >= NSEG) return;
    int ex = g_scan[i] - g_cnt[i] + g_boff[i >> 10];   // exclusive start
    g_start[i] = ex;
    g_cursor[i] = ex;
}

__global__ void k_scatter(const int* __restrict__ ei, const int* __restrict__ ea) {
    int e = blockIdx.x * blockDim.x + threadIdx.x;
    if (e >= EE) return;
    int seg = ei[EE + e] * KK + (ea[e] - 1);
    int pos = atomicAdd(&g_cursor[seg], 1);
    g_srcs[pos] = ei[e];             // store source node id directly
}

// ---------------- segmented gated aggregation (CSR, MLP=4) -------------------
__global__ __launch_bounds__(192) void k_agg() {
    int n  = blockIdx.x;
    int tx = threadIdx.x;            // feature dim 0..63
    int k  = threadIdx.y;            // hop 0..2

    float dx = g_Dx[n * DD + tx];
    const float* __restrict__ Bk = g_Bx + k * NN * DD;

    int seg = n * KK + k;
    const int* __restrict__ src = g_srcs + g_start[seg];
    int cnt = g_cnt[seg];

    float num = 0.f, den = 0.f;
    int h = 0;
    for (; h + 4 <= cnt; h += 4) {
        int j0 = src[h], j1 = src[h + 1], j2 = src[h + 2], j3 = src[h + 3];
        float b0 = Bk[j0 * DD + tx];
        float b1 = Bk[j1 * DD + tx];
        float b2 = Bk[j2 * DD + tx];
        float b3 = Bk[j3 * DD + tx];
        float s;
        s = 1.f / (1.f + __expf(-(dx + b0))); num += s * b0; den += s;
        s = 1.f / (1.f + __expf(-(dx + b1))); num += s * b1; den += s;
        s = 1.f / (1.f + __expf(-(dx + b2))); num += s * b2; den += s;
        s = 1.f / (1.f + __expf(-(dx + b3))); num += s * b3; den += s;
    }
    for (; h < cnt; h++) {
        int j = src[h];
        float b = Bk[j * DD + tx];
        float s = 1.f / (1.f + __expf(-(dx + b)));
        num += s * b; den += s;
    }
    float eta = num / (den + 1e-6f);

    __shared__ float sh[KK][DD];
    sh[k][tx] = eta;
    __syncthreads();
    if (k == 0) {
        float xn = g_Ax[n * DD + tx]
                 + (1.f / 3.f) * (sh[0][tx] + sh[1][tx] + sh[2][tx]);
        g_xnew[n * DD + tx] = xn;
    }
}

// ---------------- BN statistics (two-level reduction) ------------------------
__global__ __launch_bounds__(256) void k_stats() {
    int d = threadIdx.x & 63;
    int r = threadIdx.x >> 6;
    float s = 0.f, s2 = 0.f;
    for (int n = blockIdx.x * 4 + r; n < NN; n += gridDim.x * 4) {
        float x = g_xnew[n * DD + d];
        s += x; s2 += x * x;
    }
    __shared__ float sh1[256], sh2[256];
    sh1[threadIdx.x] = s; sh2[threadIdx.x] = s2;
    __syncthreads();
    if (threadIdx.x < 64) {
        float a = sh1[threadIdx.x] + sh1[threadIdx.x + 64]
                + sh1[threadIdx.x + 128] + sh1[threadIdx.x + 192];
        float b = sh2[threadIdx.x] + sh2[threadIdx.x + 64]
                + sh2[threadIdx.x + 128] + sh2[threadIdx.x + 192];
        atomicAdd(&g_sum[d], a);
        atomicAdd(&g_sq[d], b);
    }
}

// ---------------- BatchNorm + ReLU epilogue ----------------------------------
__global__ void k_final(const float* __restrict__ gamma,
                        const float* __restrict__ beta,
                        float* __restrict__ out) {
    int i = blockIdx.x * blockDim.x + threadIdx.x;
    if (i >= NN * DD) return;
    int d = i & 63;
    float mean = g_sum[d] * (1.f / NN);
    float var  = g_sq[d] * (1.f / NN) - mean * mean;   // biased var
    float x = g_xnew[i];
    float y = gamma[d] * (x - mean) * rsqrtf(var + 1e-5f) + beta[d];
    out[i] = fmaxf(y, 0.f);
}

// ---------------- launcher ---------------------------------------------------
extern "C" void kernel_launch(void* const* d_in, const int* in_sizes, int n_in,
                              void* d_out, int out_size) {
    const float* xs    = (const float*)d_in[0];
    const int*   ei    = (const int*)  d_in[1];
    const int*   ea    = (const int*)  d_in[2];
    const float* Wa    = (const float*)d_in[3];
    const float* ba    = (const float*)d_in[4];
    const float* Wd    = (const float*)d_in[5];
    const float* bd    = (const float*)d_in[6];
    const float* Wb    = (const float*)d_in[7];
    const float* bb    = (const float*)d_in[8];
    const float* gamma = (const float*)d_in[9];
    const float* beta  = (const float*)d_in[10];
    float* out = (float*)d_out;

    k_init   <<<(NSEG_PAD + 255) / 256, 256>>>();
    k_gemm   <<<(NN + 63) / 64, 128>>>(xs, Wa, ba, Wd, bd, Wb, bb);
    k_hist   <<<(EE + 255) / 256, 256>>>(ei, ea);
    k_scanb  <<<NBLK_SCAN, SCAN_BS>>>();
    k_scant  <<<1, 256>>>();
    k_scana  <<<(NSEG + 255) / 256, 256>>>();
    k_scatter<<<(EE + 255) / 256, 256>>>(ei, ea);
    k_agg    <<<NN, dim3(64, 3)>>>();
    k_stats  <<<232, 256>>>();
    k_final  <<<(NN * DD + 255) / 256, 256>>>(gamma, beta, out);
}

// round 8
// speedup vs baseline: 1.4804x; 1.1482x over previous
#include <cuda_runtime.h>

// Problem constants (fixed by the reference)
#define NN 50000
#define EE 800000
#define DD 64
#define KK 3
#define NSEG (NN * KK)          // 150000
#define SCAN_BS 1024
#define NBLK_SCAN ((NSEG + SCAN_BS - 1) / SCAN_BS)   // 147
#define NSEG_PAD (NBLK_SCAN * SCAN_BS)               // 150528

typedef unsigned long long ull;

// ---------------- scratch (static __device__ arrays; no allocation) ----------
__device__ float g_Ax[NN * DD];
__device__ float g_Dx[NN * DD];
__device__ float g_Bx[KK * NN * DD];
__device__ float g_xnew[NN * DD];
__device__ int   g_cnt[NSEG_PAD];
__device__ int   g_scan[NSEG_PAD];
__device__ int   g_btot[NBLK_SCAN];
__device__ int   g_boff[NBLK_SCAN];
__device__ int   g_start[NSEG];
__device__ int   g_cursor[NSEG];
__device__ int   g_srcs[EE];
__device__ float g_sum[DD];
__device__ float g_sq[DD];

// ---------------- kernel 0: reset per-launch state ---------------------------
__global__ void k_init() {
    int i = blockIdx.x * blockDim.x + threadIdx.x;
    if (i < NSEG_PAD) g_cnt[i] = 0;
    if (i < DD) { g_sum[i] = 0.f; g_sq[i] = 0.f; }
}

// ---------------- f32x2 packed-FMA helpers -----------------------------------
__device__ __forceinline__ void ffma2(ull& d, ull a, ull b) {
    asm("fma.rn.f32x2 %0, %1, %2, %0;" : "+l"(d) : "l"(a), "l"(b));
}
__device__ __forceinline__ ull pack_dup(float x) {
    ull r;
    asm("mov.b64 %0, {%1, %1};" : "=l"(r) : "f"(x));
    return r;
}
__device__ __forceinline__ ull pack2(float lo, float hi) {
    ull r;
    asm("mov.b64 %0, {%1, %2};" : "=l"(r) : "f"(lo), "f"(hi));
    return r;
}
__device__ __forceinline__ void unpack2(float& lo, float& hi, ull v) {
    asm("mov.b64 {%0, %1}, %2;" : "=f"(lo), "=f"(hi) : "l"(v));
}

// ---------------- kernel 1: fused 5x GEMM ------------------------------------
// 64 threads/block, 64-node tile. Thread = 8 nodes x 8 features.
// Per d: 2 LDS.128 (W row slice) + 8 LDS.32 (x) feed 32 FFMA2 -> FMA-pipe bound.
__device__ __forceinline__ void gemm_job(
    float (*__restrict__ xsh)[65], float (*__restrict__ Wsh)[68],
    const float* __restrict__ xg,   // global x base, or nullptr to reuse tile
    const float* __restrict__ W, const float* __restrict__ b,
    float* __restrict__ out, int nb)
{
    int tx = threadIdx.x;
    int pg = tx & 7;                 // feature group: 8*pg .. 8*pg+7
    int ng = tx >> 3;                // node group:    8*ng .. 8*ng+7

    __syncthreads();                 // protect previous job's Wsh/xsh use
    if (xg) {
        for (int idx = tx; idx < 64 * DD; idx += 64) {
            int n = idx >> 6, d = idx & 63;
            int gn = nb + n;
            xsh[n][d] = (gn < NN) ? xg[gn * DD + d] : 0.f;
        }
    }
    for (int idx = tx; idx < DD * DD; idx += 64)
        Wsh[idx >> 6][idx & 63] = W[idx];
    __syncthreads();

    ull acc[8][4];
    #pragma unroll
    for (int m = 0; m < 8; m++)
        #pragma unroll
        for (int pp = 0; pp < 4; pp++) acc[m][pp] = 0ull;

    #pragma unroll 8
    for (int d = 0; d < DD; d++) {
        float4 wa = *(const float4*)&Wsh[d][8 * pg];
        float4 wb = *(const float4*)&Wsh[d][8 * pg + 4];
        ull w0 = pack2(wa.x, wa.y), w1 = pack2(wa.z, wa.w);
        ull w2 = pack2(wb.x, wb.y), w3 = pack2(wb.z, wb.w);
        #pragma unroll
        for (int m = 0; m < 8; m++) {
            ull x2 = pack_dup(xsh[ng * 8 + m][d]);
            ffma2(acc[m][0], x2, w0);
            ffma2(acc[m][1], x2, w1);
            ffma2(acc[m][2], x2, w2);
            ffma2(acc[m][3], x2, w3);
        }
    }

    float b0 = b[8 * pg],     b1 = b[8 * pg + 1], b2 = b[8 * pg + 2], b3 = b[8 * pg + 3];
    float b4 = b[8 * pg + 4], b5 = b[8 * pg + 5], b6 = b[8 * pg + 6], b7 = b[8 * pg + 7];
    #pragma unroll
    for (int m = 0; m < 8; m++) {
        int n = nb + ng * 8 + m;
        if (n >= NN) continue;
        float v0, v1, v2, v3, v4, v5, v6, v7;
        unpack2(v0, v1, acc[m][0]);
        unpack2(v2, v3, acc[m][1]);
        unpack2(v4, v5, acc[m][2]);
        unpack2(v6, v7, acc[m][3]);
        float4 o0 = make_float4(v0 + b0, v1 + b1, v2 + b2, v3 + b3);
        float4 o1 = make_float4(v4 + b4, v5 + b5, v6 + b6, v7 + b7);
        *(float4*)&out[n * DD + 8 * pg]     = o0;
        *(float4*)&out[n * DD + 8 * pg + 4] = o1;
    }
}

__global__ __launch_bounds__(64) void k_gemm(
    const float* __restrict__ xs,
    const float* __restrict__ Wa, const float* __restrict__ ba,
    const float* __restrict__ Wd, const float* __restrict__ bd,
    const float* __restrict__ Wb, const float* __restrict__ bb)
{
    __shared__ float xsh[64][65];    // 16.6 KB
    __shared__ float Wsh[64][68];    // 17.4 KB (68: rows 16B-aligned for LDS.128)
    int nb = blockIdx.x * 64;

    const float* x2g = xs + 2 * NN * DD;
    const float* x1g = xs + 1 * NN * DD;
    const float* x0g = xs;

    // Ax, Dx, Bx0 share xs[2]; Bx1 <- xs[1]; Bx2 <- xs[0]
    gemm_job(xsh, Wsh, x2g, Wa,             ba,          g_Ax,             nb);
    gemm_job(xsh, Wsh, 0,   Wd,             bd,          g_Dx,             nb);
    gemm_job(xsh, Wsh, 0,   Wb,             bb,          g_Bx,             nb);
    gemm_job(xsh, Wsh, x1g, Wb +     DD*DD, bb +     DD, g_Bx +     NN*DD, nb);
    gemm_job(xsh, Wsh, x0g, Wb + 2 * DD*DD, bb + 2 * DD, g_Bx + 2 * NN*DD, nb);
}

// ---------------- CSR build: histogram -> scan -> scatter --------------------
__global__ void k_hist(const int* __restrict__ ei, const int* __restrict__ ea) {
    int e = blockIdx.x * blockDim.x + threadIdx.x;
    if (e >= EE) return;
    int seg = ei[EE + e] * KK + (ea[e] - 1);
    atomicAdd(&g_cnt[seg], 1);
}

__global__ __launch_bounds__(SCAN_BS) void k_scanb() {
    __shared__ int sh[SCAN_BS];
    int t = threadIdx.x;
    int i = blockIdx.x * SCAN_BS + t;
    int v = g_cnt[i];
    sh[t] = v;
    __syncthreads();
    for (int o = 1; o < SCAN_BS; o <<= 1) {
        int a = (t >= o) ? sh[t - o] : 0;
        __syncthreads();
        sh[t] += a;
        __syncthreads();
    }
    g_scan[i] = sh[t];
    if (t == SCAN_BS - 1) g_btot[blockIdx.x] = sh[t];
}

__global__ __launch_bounds__(256) void k_scant() {
    __shared__ int sh[256];
    int t = threadIdx.x;
    int v = (t < NBLK_SCAN) ? g_btot[t] : 0;
    sh[t] = v;
    __syncthreads();
    for (int o = 1; o < 256; o <<= 1) {
        int a = (t >= o) ? sh[t - o] : 0;
        __syncthreads();
        sh[t] += a;
        __syncthreads();
    }
    if (t < NBLK_SCAN) g_boff[t] = sh[t] - v;
}

__global__ void k_scana() {
    int i = blockIdx.x * blockDim.x + threadIdx.x;
    if (i >= NSEG) return;
    int ex = g_scan[i] - g_cnt[i] + g_boff[i >> 10];
    g_start[i] = ex;
    g_cursor[i] = ex;
}

__global__ void k_scatter(const int* __restrict__ ei, const int* __restrict__ ea) {
    int e = blockIdx.x * blockDim.x + threadIdx.x;
    if (e >= EE) return;
    int seg = ei[EE + e] * KK + (ea[e] - 1);
    int pos = atomicAdd(&g_cursor[seg], 1);
    g_srcs[pos] = ei[e];
}

// ---------------- segmented gated aggregation (CSR, 2 nodes/block) -----------
__global__ __launch_bounds__(384) void k_agg() {
    int tx   = threadIdx.x;           // feature 0..63
    int slot = threadIdx.y;           // 0..5
    int k    = slot % KK;
    int ln   = slot / KK;             // local node 0..1
    int n    = blockIdx.x * 2 + ln;   // NN even -> always < NN

    __shared__ float sh[2][KK][DD];

    float dx = g_Dx[n * DD + tx];
    const float* __restrict__ Bk = g_Bx + k * NN * DD;

    int seg = n * KK + k;
    const int* __restrict__ src = g_srcs + g_start[seg];
    int cnt = g_cnt[seg];

    float num = 0.f, den = 0.f;
    int h = 0;
    for (; h + 4 <= cnt; h += 4) {
        int j0 = src[h], j1 = src[h + 1], j2 = src[h + 2], j3 = src[h + 3];
        float b0 = Bk[j0 * DD + tx];
        float b1 = Bk[j1 * DD + tx];
        float b2 = Bk[j2 * DD + tx];
        float b3 = Bk[j3 * DD + tx];
        float s;
        s = 1.f / (1.f + __expf(-(dx + b0))); num += s * b0; den += s;
        s = 1.f / (1.f + __expf(-(dx + b1))); num += s * b1; den += s;
        s = 1.f / (1.f + __expf(-(dx + b2))); num += s * b2; den += s;
        s = 1.f / (1.f + __expf(-(dx + b3))); num += s * b3; den += s;
    }
    for (; h < cnt; h++) {
        int j = src[h];
        float b = Bk[j * DD + tx];
        float s = 1.f / (1.f + __expf(-(dx + b)));
        num += s * b; den += s;
    }
    sh[ln][k][tx] = num / (den + 1e-6f);
    __syncthreads();

    if (slot < 2) {                   // slot as local node id
        int nn = blockIdx.x * 2 + slot;
        float xn = g_Ax[nn * DD + tx]
                 + (1.f / 3.f) * (sh[slot][0][tx] + sh[slot][1][tx] + sh[slot][2][tx]);
        g_xnew[nn * DD + tx] = xn;
    }
}

// ---------------- BN statistics (two-level reduction) ------------------------
__global__ __launch_bounds__(256) void k_stats() {
    int d = threadIdx.x & 63;
    int r = threadIdx.x >> 6;
    float s = 0.f, s2 = 0.f;
    for (int n = blockIdx.x * 4 + r; n < NN; n += gridDim.x * 4) {
        float x = g_xnew[n * DD + d];
        s += x; s2 += x * x;
    }
    __shared__ float sh1[256], sh2[256];
    sh1[threadIdx.x] = s; sh2[threadIdx.x] = s2;
    __syncthreads();
    if (threadIdx.x < 64) {
        float a = sh1[threadIdx.x] + sh1[threadIdx.x + 64]
                + sh1[threadIdx.x + 128] + sh1[threadIdx.x + 192];
        float b = sh2[threadIdx.x] + sh2[threadIdx.x + 64]
                + sh2[threadIdx.x + 128] + sh2[threadIdx.x + 192];
        atomicAdd(&g_sum[d], a);
        atomicAdd(&g_sq[d], b);
    }
}

// ---------------- BatchNorm + ReLU epilogue ----------------------------------
__global__ void k_final(const float* __restrict__ gamma,
                        const float* __restrict__ beta,
                        float* __restrict__ out) {
    int i = blockIdx.x * blockDim.x + threadIdx.x;
    if (i >= NN * DD) return;
    int d = i & 63;
    float mean = g_sum[d] * (1.f / NN);
    float var  = g_sq[d] * (1.f / NN) - mean * mean;   // biased var
    float x = g_xnew[i];
    float y = gamma[d] * (x - mean) * rsqrtf(var + 1e-5f) + beta[d];
    out[i] = fmaxf(y, 0.f);
}

// ---------------- launcher ---------------------------------------------------
extern "C" void kernel_launch(void* const* d_in, const int* in_sizes, int n_in,
                              void* d_out, int out_size) {
    const float* xs    = (const float*)d_in[0];
    const int*   ei    = (const int*)  d_in[1];
    const int*   ea    = (const int*)  d_in[2];
    const float* Wa    = (const float*)d_in[3];
    const float* ba    = (const float*)d_in[4];
    const float* Wd    = (const float*)d_in[5];
    const float* bd    = (const float*)d_in[6];
    const float* Wb    = (const float*)d_in[7];
    const float* bb    = (const float*)d_in[8];
    const float* gamma = (const float*)d_in[9];
    const float* beta  = (const float*)d_in[10];
    float* out = (float*)d_out;

    k_init   <<<(NSEG_PAD + 255) / 256, 256>>>();
    k_gemm   <<<(NN + 63) / 64, 64>>>(xs, Wa, ba, Wd, bd, Wb, bb);
    k_hist   <<<(EE + 255) / 256, 256>>>(ei, ea);
    k_scanb  <<<NBLK_SCAN, SCAN_BS>>>();
    k_scant  <<<1, 256>>>();
    k_scana  <<<(NSEG + 255) / 256, 256>>>();
    k_scatter<<<(EE + 255) / 256, 256>>>(ei, ea);
    k_agg    <<<NN / 2, dim3(64, 6)>>>();
    k_stats  <<<232, 256>>>();
    k_final  <<<(NN * DD + 255) / 256, 256>>>(gamma, beta, out);
}

// round 9
// speedup vs baseline: 1.6017x; 1.0819x over previous
#include <cuda_runtime.h>

// Problem constants (fixed by the reference)
#define NN 50000
#define EE 800000
#define DD 64
#define KK 3
#define NSEG (NN * KK)          // 150000
#define SCAN_BS 1024
#define NBLK_SCAN ((NSEG + SCAN_BS - 1) / SCAN_BS)   // 147
#define NSEG_PAD (NBLK_SCAN * SCAN_BS)               // 150528

typedef unsigned long long ull;

// ---------------- scratch (static __device__ arrays; no allocation) ----------
__device__ float g_Ax[NN * DD];
__device__ float g_Dx[NN * DD];
__device__ float g_Bx[KK * NN * DD];
__device__ float g_xnew[NN * DD];
__device__ int   g_cnt[NSEG_PAD];
__device__ int   g_scan[NSEG_PAD];
__device__ int   g_btot[NBLK_SCAN];
__device__ int   g_boff[NBLK_SCAN];
__device__ int   g_start[NSEG];
__device__ int   g_cursor[NSEG];
__device__ int   g_srcs[EE];
__device__ float g_sum[DD];
__device__ float g_sq[DD];

// ---------------- kernel 0: reset per-launch state ---------------------------
__global__ void k_init() {
    int i = blockIdx.x * blockDim.x + threadIdx.x;
    if (i < NSEG_PAD) g_cnt[i] = 0;
    if (i < DD) { g_sum[i] = 0.f; g_sq[i] = 0.f; }
}

// ---------------- f32x2 packed-FMA helpers -----------------------------------
__device__ __forceinline__ void ffma2(ull& d, ull a, ull b) {
    asm("fma.rn.f32x2 %0, %1, %2, %0;" : "+l"(d) : "l"(a), "l"(b));
}
__device__ __forceinline__ ull pack_dup(float x) {
    ull r;
    asm("mov.b64 %0, {%1, %1};" : "=l"(r) : "f"(x));
    return r;
}
__device__ __forceinline__ void unpack2(float& lo, float& hi, ull v) {
    asm("mov.b64 {%0, %1}, %2;" : "=f"(lo), "=f"(hi) : "l"(v));
}

// ---------------- kernel 1: fused 5x GEMM ------------------------------------
// 64 threads/block, 64-node tile. Thread = 8 nodes x 8 features.
// W slices read directly as ulonglong2 (LDS.128 -> aligned reg pairs, no MOVs).
__device__ __forceinline__ void gemm_job(
    float (*__restrict__ xsh)[65], float (*__restrict__ Wsh)[68],
    const float* __restrict__ xg,   // global x base, or nullptr to reuse tile
    const float* __restrict__ W, const float* __restrict__ b,
    float* __restrict__ out, int nb)
{
    int tx = threadIdx.x;
    int pg = tx & 7;                 // feature group: 8*pg .. 8*pg+7
    int ng = tx >> 3;                // node group:    8*ng .. 8*ng+7

    __syncthreads();                 // protect previous job's Wsh/xsh use
    if (xg) {
        // 64 nodes x 64 feats: float4 LDG + 4x STS.32 (xsh stride 65 keeps
        // the compute-phase reads conflict-free, so stores stay scalar)
        #pragma unroll
        for (int it = 0; it < 16; it++) {
            int idx = it * 64 + tx;           // 0..1023 float4 tiles
            int n = idx >> 4, c4 = (idx & 15) * 4;
            int gn = nb + n;
            float4 v = (gn < NN) ? *(const float4*)&xg[gn * DD + c4]
                                 : make_float4(0.f, 0.f, 0.f, 0.f);
            xsh[n][c4]     = v.x;
            xsh[n][c4 + 1] = v.y;
            xsh[n][c4 + 2] = v.z;
            xsh[n][c4 + 3] = v.w;
        }
    }
    // W fill: float4 LDG + float4 STS (rows 16B-aligned: stride 68)
    #pragma unroll
    for (int it = 0; it < 16; it++) {
        int idx = it * 64 + tx;               // 0..1023 float4 tiles
        int r = idx >> 4, c4 = (idx & 15) * 4;
        *(float4*)&Wsh[r][c4] = *(const float4*)&W[r * DD + c4];
    }
    __syncthreads();

    ull acc[8][4];
    #pragma unroll
    for (int m = 0; m < 8; m++)
        #pragma unroll
        for (int pp = 0; pp < 4; pp++) acc[m][pp] = 0ull;

    #pragma unroll 8
    for (int d = 0; d < DD; d++) {
        ulonglong2 wa = *(const ulonglong2*)&Wsh[d][8 * pg];      // feats 0..3
        ulonglong2 wb = *(const ulonglong2*)&Wsh[d][8 * pg + 4];  // feats 4..7
        #pragma unroll
        for (int m = 0; m < 8; m++) {
            ull x2 = pack_dup(xsh[ng * 8 + m][d]);
            ffma2(acc[m][0], x2, wa.x);
            ffma2(acc[m][1], x2, wa.y);
            ffma2(acc[m][2], x2, wb.x);
            ffma2(acc[m][3], x2, wb.y);
        }
    }

    float b0 = b[8 * pg],     b1 = b[8 * pg + 1], b2 = b[8 * pg + 2], b3 = b[8 * pg + 3];
    float b4 = b[8 * pg + 4], b5 = b[8 * pg + 5], b6 = b[8 * pg + 6], b7 = b[8 * pg + 7];
    #pragma unroll
    for (int m = 0; m < 8; m++) {
        int n = nb + ng * 8 + m;
        if (n >= NN) continue;
        float v0, v1, v2, v3, v4, v5, v6, v7;
        unpack2(v0, v1, acc[m][0]);
        unpack2(v2, v3, acc[m][1]);
        unpack2(v4, v5, acc[m][2]);
        unpack2(v6, v7, acc[m][3]);
        float4 o0 = make_float4(v0 + b0, v1 + b1, v2 + b2, v3 + b3);
        float4 o1 = make_float4(v4 + b4, v5 + b5, v6 + b6, v7 + b7);
        *(float4*)&out[n * DD + 8 * pg]     = o0;
        *(float4*)&out[n * DD + 8 * pg + 4] = o1;
    }
}

__global__ __launch_bounds__(64) void k_gemm(
    const float* __restrict__ xs,
    const float* __restrict__ Wa, const float* __restrict__ ba,
    const float* __restrict__ Wd, const float* __restrict__ bd,
    const float* __restrict__ Wb, const float* __restrict__ bb)
{
    __shared__ float xsh[64][65];    // 16.6 KB (65: compute reads conflict-free)
    __shared__ float Wsh[64][68];    // 17.4 KB (68: rows 16B-aligned)
    int nb = blockIdx.x * 64;

    const float* x2g = xs + 2 * NN * DD;
    const float* x1g = xs + 1 * NN * DD;
    const float* x0g = xs;

    // Ax, Dx, Bx0 share xs[2]; Bx1 <- xs[1]; Bx2 <- xs[0]
    gemm_job(xsh, Wsh, x2g, Wa,             ba,          g_Ax,             nb);
    gemm_job(xsh, Wsh, 0,   Wd,             bd,          g_Dx,             nb);
    gemm_job(xsh, Wsh, 0,   Wb,             bb,          g_Bx,             nb);
    gemm_job(xsh, Wsh, x1g, Wb +     DD*DD, bb +     DD, g_Bx +     NN*DD, nb);
    gemm_job(xsh, Wsh, x0g, Wb + 2 * DD*DD, bb + 2 * DD, g_Bx + 2 * NN*DD, nb);
}

// ---------------- CSR build: histogram -> scan -> scatter --------------------
__global__ void k_hist(const int* __restrict__ ei, const int* __restrict__ ea) {
    int e = blockIdx.x * blockDim.x + threadIdx.x;
    if (e >= EE) return;
    int seg = ei[EE + e] * KK + (ea[e] - 1);
    atomicAdd(&g_cnt[seg], 1);
}

__global__ __launch_bounds__(SCAN_BS) void k_scanb() {
    __shared__ int sh[SCAN_BS];
    int t = threadIdx.x;
    int i = blockIdx.x * SCAN_BS + t;
    int v = g_cnt[i];
    sh[t] = v;
    __syncthreads();
    for (int o = 1; o < SCAN_BS; o <<= 1) {
        int a = (t >= o) ? sh[t - o] : 0;
        __syncthreads();
        sh[t] += a;
        __syncthreads();
    }
    g_scan[i] = sh[t];
    if (t == SCAN_BS - 1) g_btot[blockIdx.x] = sh[t];
}

__global__ __launch_bounds__(256) void k_scant() {
    __shared__ int sh[256];
    int t = threadIdx.x;
    int v = (t < NBLK_SCAN) ? g_btot[t] : 0;
    sh[t] = v;
    __syncthreads();
    for (int o = 1; o < 256; o <<= 1) {
        int a = (t >= o) ? sh[t - o] : 0;
        __syncthreads();
        sh[t] += a;
        __syncthreads();
    }
    if (t < NBLK_SCAN) g_boff[t] = sh[t] - v;
}

__global__ void k_scana() {
    int i = blockIdx.x * blockDim.x + threadIdx.x;
    if (i >= NSEG) return;
    int ex = g_scan[i] - g_cnt[i] + g_boff[i >> 10];
    g_start[i] = ex;
    g_cursor[i] = ex;
}

__global__ void k_scatter(const int* __restrict__ ei, const int* __restrict__ ea) {
    int e = blockIdx.x * blockDim.x + threadIdx.x;
    if (e >= EE) return;
    int seg = ei[EE + e] * KK + (ea[e] - 1);
    int pos = atomicAdd(&g_cursor[seg], 1);
    g_srcs[pos] = ei[e];
}

// ---------------- segmented gated aggregation (CSR, 2 nodes/block) -----------
__global__ __launch_bounds__(384) void k_agg() {
    int tx   = threadIdx.x;           // feature 0..63
    int slot = threadIdx.y;           // 0..5
    int k    = slot % KK;
    int ln   = slot / KK;             // local node 0..1
    int n    = blockIdx.x * 2 + ln;   // NN even -> always < NN

    __shared__ float sh[2][KK][DD];

    float dx = g_Dx[n * DD + tx];
    const float* __restrict__ Bk = g_Bx + k * NN * DD;

    int seg = n * KK + k;
    const int* __restrict__ src = g_srcs + g_start[seg];
    int cnt = g_cnt[seg];

    float num = 0.f, den = 0.f;
    int h = 0;
    for (; h + 4 <= cnt; h += 4) {
        int j0 = src[h], j1 = src[h + 1], j2 = src[h + 2], j3 = src[h + 3];
        float b0 = Bk[j0 * DD + tx];
        float b1 = Bk[j1 * DD + tx];
        float b2 = Bk[j2 * DD + tx];
        float b3 = Bk[j3 * DD + tx];
        float s;
        s = 1.f / (1.f + __expf(-(dx + b0))); num += s * b0; den += s;
        s = 1.f / (1.f + __expf(-(dx + b1))); num += s * b1; den += s;
        s = 1.f / (1.f + __expf(-(dx + b2))); num += s * b2; den += s;
        s = 1.f / (1.f + __expf(-(dx + b3))); num += s * b3; den += s;
    }
    for (; h < cnt; h++) {
        int j = src[h];
        float b = Bk[j * DD + tx];
        float s = 1.f / (1.f + __expf(-(dx + b)));
        num += s * b; den += s;
    }
    sh[ln][k][tx] = num / (den + 1e-6f);
    __syncthreads();

    if (slot < 2) {                   // slot as local node id
        int nn = blockIdx.x * 2 + slot;
        float xn = g_Ax[nn * DD + tx]
                 + (1.f / 3.f) * (sh[slot][0][tx] + sh[slot][1][tx] + sh[slot][2][tx]);
        g_xnew[nn * DD + tx] = xn;
    }
}

// ---------------- BN statistics (two-level reduction) ------------------------
__global__ __launch_bounds__(256) void k_stats() {
    int d = threadIdx.x & 63;
    int r = threadIdx.x >> 6;
    float s = 0.f, s2 = 0.f;
    for (int n = blockIdx.x * 4 + r; n < NN; n += gridDim.x * 4) {
        float x = g_xnew[n * DD + d];
        s += x; s2 += x * x;
    }
    __shared__ float sh1[256], sh2[256];
    sh1[threadIdx.x] = s; sh2[threadIdx.x] = s2;
    __syncthreads();
    if (threadIdx.x < 64) {
        float a = sh1[threadIdx.x] + sh1[threadIdx.x + 64]
                + sh1[threadIdx.x + 128] + sh1[threadIdx.x + 192];
        float b = sh2[threadIdx.x] + sh2[threadIdx.x + 64]
                + sh2[threadIdx.x + 128] + sh2[threadIdx.x + 192];
        atomicAdd(&g_sum[d], a);
        atomicAdd(&g_sq[d], b);
    }
}

// ---------------- BatchNorm + ReLU epilogue ----------------------------------
__global__ void k_final(const float* __restrict__ gamma,
                        const float* __restrict__ beta,
                        float* __restrict__ out) {
    int i = blockIdx.x * blockDim.x + threadIdx.x;
    if (i >= NN * DD) return;
    int d = i & 63;
    float mean = g_sum[d] * (1.f / NN);
    float var  = g_sq[d] * (1.f / NN) - mean * mean;   // biased var
    float x = g_xnew[i];
    float y = gamma[d] * (x - mean) * rsqrtf(var + 1e-5f) + beta[d];
    out[i] = fmaxf(y, 0.f);
}

// ---------------- launcher ---------------------------------------------------
// Order chosen so the 4th launch (the one ncu captures) is k_gemm.
// Dependencies: hist needs init; scanb<-hist; scant<-scanb; scana<-scant;
// scatter<-scana; agg<-{gemm, scatter}; stats<-agg; final<-stats.
extern "C" void kernel_launch(void* const* d_in, const int* in_sizes, int n_in,
                              void* d_out, int out_size) {
    const float* xs    = (const float*)d_in[0];
    const int*   ei    = (const int*)  d_in[1];
    const int*   ea    = (const int*)  d_in[2];
    const float* Wa    = (const float*)d_in[3];
    const float* ba    = (const float*)d_in[4];
    const float* Wd    = (const float*)d_in[5];
    const float* bd    = (const float*)d_in[6];
    const float* Wb    = (const float*)d_in[7];
    const float* bb    = (const float*)d_in[8];
    const float* gamma = (const float*)d_in[9];
    const float* beta  = (const float*)d_in[10];
    float* out = (float*)d_out;

    k_init   <<<(NSEG_PAD + 255) / 256, 256>>>();
    k_hist   <<<(EE + 255) / 256, 256>>>(ei, ea);
    k_scanb  <<<NBLK_SCAN, SCAN_BS>>>();
    k_gemm   <<<(NN + 63) / 64, 64>>>(xs, Wa, ba, Wd, bd, Wb, bb);   // 4th: profiled
    k_scant  <<<1, 256>>>();
    k_scana  <<<(NSEG + 255) / 256, 256>>>();
    k_scatter<<<(EE + 255) / 256, 256>>>(ei, ea);
    k_agg    <<<NN / 2, dim3(64, 6)>>>();
    k_stats  <<<232, 256>>>();
    k_final  <<<(NN * DD + 255) / 256, 256>>>(gamma, beta, out);
}